// round 2
// baseline (speedup 1.0000x reference)
#include <cuda_runtime.h>
#include <cuda_bf16.h>
#include <cstdint>

// ---------------- problem constants ----------------
#define BB   32
#define TT   128
#define LCC  16
#define EE   256
#define ECC  64
#define HCC  128   // char bilstm out (64 per dir)
#define HH   512   // word bilstm out (256 per dir)
#define KK   12
#define START_T 10
#define STOP_T  11
#define NEGV -10000.0f

#define BT   (BB*TT)            // 4096
#define MCH  (BT*LCC)           // 65536 char rows
#define INW  (EE + HCC)         // 384
#define HW   256                // word hidden per dir
#define GW   1024               // 4*HW
#define HCD  64                 // char hidden per dir
#define GC   256                // 4*HCD

// ---------------- scratch (device globals; no allocs allowed) ----------------
__device__ float g_xprojc[(size_t)MCH * GC];     // char fwd input proj  (67MB)
__device__ float g_bg[(size_t)BT * GC];          // char bwd last-step gates
__device__ float g_chout[(size_t)BT * HCC];      // char features per word
__device__ float g_wx[(size_t)BT * INW];         // word lstm input
__device__ float g_wpf[(size_t)BT * GW];         // word fwd input proj
__device__ float g_wpb[(size_t)BT * GW];         // word bwd input proj
__device__ float g_h[2 * 2 * HW * BB];           // [parity][dir][j][b] hidden double buffer
__device__ float g_wh[(size_t)2 * BT * HW];      // [dir][b*T+t][j] all hiddens
__device__ float g_feats[(size_t)BT * KK];

// barrier state (reset every launch by reset_bar -> deterministic)
__device__ volatile unsigned g_gen = 0;
__device__ unsigned g_cnt = 0;

#define NBW 128   // blocks in word-lstm persistent kernel (<=148, all resident)

__device__ __forceinline__ float sigf(float x) { return 1.0f / (1.0f + expf(-x)); }

// ---------------- generic tiled GEMM: C[M,N] = A[M,K] @ W[N,K]^T + bias ----------------
// A optionally gathered: row m -> emb[idx[m*idx_stride + idx_off]]
template <bool GATHER>
__global__ void gemm_tn(const float* __restrict__ Aorig, const int* __restrict__ idx,
                        int idx_stride, int idx_off,
                        const float* __restrict__ W, const float* __restrict__ bias,
                        float* __restrict__ C, int M, int N, int Kd)
{
    __shared__ __align__(16) float As[16][64];
    __shared__ __align__(16) float Bs[16][64];
    const int m0 = blockIdx.y * 64;
    const int n0 = blockIdx.x * 64;
    const int tid = threadIdx.x;
    const int tx = tid & 15, ty = tid >> 4;

    float acc[4][4];
#pragma unroll
    for (int i = 0; i < 4; i++)
#pragma unroll
        for (int j = 0; j < 4; j++) acc[i][j] = 0.0f;

    for (int k0 = 0; k0 < Kd; k0 += 16) {
#pragma unroll
        for (int i = 0; i < 4; i++) {
            int e = tid + i * 256;
            int row = e >> 4, col = e & 15;
            const float* arow;
            if (GATHER) {
                int r = idx[(m0 + row) * idx_stride + idx_off];
                arow = Aorig + (size_t)r * Kd;
            } else {
                arow = Aorig + (size_t)(m0 + row) * Kd;
            }
            As[col][row] = arow[k0 + col];
            Bs[col][row] = W[(size_t)(n0 + row) * Kd + k0 + col];
        }
        __syncthreads();
#pragma unroll
        for (int k = 0; k < 16; k++) {
            float4 av = *(const float4*)&As[k][ty << 2];
            float4 bv = *(const float4*)&Bs[k][tx << 2];
            float a4[4] = {av.x, av.y, av.z, av.w};
            float b4[4] = {bv.x, bv.y, bv.z, bv.w};
#pragma unroll
            for (int i = 0; i < 4; i++)
#pragma unroll
                for (int j = 0; j < 4; j++) acc[i][j] += a4[i] * b4[j];
        }
        __syncthreads();
    }

#pragma unroll
    for (int i = 0; i < 4; i++) {
        int m = m0 + (ty << 2) + i;
#pragma unroll
        for (int j = 0; j < 4; j++) {
            int n = n0 + (tx << 2) + j;
            C[(size_t)m * N + n] = acc[i][j] + bias[n];
        }
    }
}

// ---------------- char forward LSTM: one block per (b,t) word ----------------
__global__ void char_fwd_kernel(const float* __restrict__ Whh, float* __restrict__ chout)
{
    const int bt = blockIdx.x;
    const int j = threadIdx.x;   // 256 threads = gate index
    __shared__ __align__(16) float hs[HCD];
    __shared__ float gs[GC];

    float4 w4[16];
    const float4* wr = (const float4*)(Whh + j * HCD);
#pragma unroll
    for (int i = 0; i < 16; i++) w4[i] = wr[i];

    float c = 0.0f;
    if (j < HCD) hs[j] = 0.0f;
    __syncthreads();

    const float* xp = g_xprojc + (size_t)bt * LCC * GC;
    for (int t = 0; t < LCC; t++) {
        float acc = xp[t * GC + j];
#pragma unroll
        for (int kk = 0; kk < 16; kk++) {
            float4 h4 = *(const float4*)&hs[kk << 2];
            acc += w4[kk].x * h4.x + w4[kk].y * h4.y + w4[kk].z * h4.z + w4[kk].w * h4.w;
        }
        gs[j] = acc;
        __syncthreads();
        if (j < HCD) {
            float gi = gs[j], gf = gs[HCD + j], gg = gs[2 * HCD + j], go = gs[3 * HCD + j];
            c = sigf(gf) * c + sigf(gi) * tanhf(gg);
            hs[j] = sigf(go) * tanhf(c);
        }
        __syncthreads();
    }
    if (j < HCD) chout[(size_t)bt * HCC + j] = hs[j];
}

// ---------------- char backward single-step (from gates) ----------------
__global__ void char_bwd_kernel(float* __restrict__ chout)
{
    int idx = blockIdx.x * blockDim.x + threadIdx.x;
    if (idx >= BT * HCD) return;
    int bt = idx / HCD, jh = idx % HCD;
    const float* g = g_bg + (size_t)bt * GC;
    float gi = g[jh], gg = g[2 * HCD + jh], go = g[3 * HCD + jh];
    float c = sigf(gi) * tanhf(gg);       // c_prev = 0 -> forget term drops
    chout[(size_t)bt * HCC + HCD + jh] = sigf(go) * tanhf(c);
}

// ---------------- build word-lstm input x = [ch, we] ----------------
__global__ void build_wx_kernel(const int* __restrict__ sentence,
                                const float* __restrict__ word_emb)
{
    int idx = blockIdx.x * blockDim.x + threadIdx.x;
    if (idx >= BT * INW) return;
    int bt = idx / INW, cpos = idx % INW;
    float v;
    if (cpos < HCC) v = g_chout[(size_t)bt * HCC + cpos];
    else            v = word_emb[(size_t)sentence[bt] * EE + (cpos - HCC)];
    g_wx[idx] = v;
}

// ---------------- barrier reset (determinism across graph replays) ----------------
__global__ void reset_bar()
{
    g_cnt = 0;
    g_gen = 0;
}

// ---------------- persistent word BiLSTM with grid barrier ----------------
// 128 blocks x 128 threads. block = (dir, 4-row chunk). thread = (row-in-chunk, batch).
// smem: 16KB weight slice [jh_l][k][gate] (float4 per k) + 32KB swizzled hidden [k][b^].
// Exactly 48KB dynamic -> no cudaFuncSetAttribute needed.
__global__ void word_lstm_kernel(const float* __restrict__ Whhf,
                                 const float* __restrict__ Whhb)
{
    extern __shared__ float sm[];
    float* ws = sm;                 // 4096 floats
    float* hs = sm + 4096;          // 8192 floats

    const int tid = threadIdx.x;          // 0..127
    const int dir = blockIdx.x >> 6;      // 0 fwd, 1 bwd
    const int chunk = blockIdx.x & 63;
    const int jh0 = chunk * 4;
    const int jh_l = tid >> 5;            // 0..3
    const int b = tid & 31;
    const int jh = jh0 + jh_l;

    const float* Whh = dir ? Whhb : Whhf;
    const float* xp  = dir ? g_wpb : g_wpf;

    // stage weight slice once: ws[((jh_l*256 + k)*4) + gate]
    for (int i = tid; i < 4096; i += 128) {
        int gate = i & 3;
        int k = (i >> 2) & 255;
        int jl = i >> 10;
        ws[i] = Whh[(size_t)((gate << 8) + jh0 + jl) * HW + k];
    }
    __syncthreads();

    const float4* wv = (const float4*)ws + (jh_l << 8);

    float c = 0.0f;
    for (int s = 0; s < TT; s++) {
        const int t = dir ? (TT - 1 - s) : s;
        float ai = 0.f, af = 0.f, ag = 0.f, ao = 0.f;
        if (s > 0) {
            // stage h (written by all blocks of this dir last step) into swizzled smem
            const float* hsrc = g_h + (((s & 1) * 2 + dir) << 13);   // [j][b]
            for (int i = tid; i < 8192; i += 128) {
                int j = i >> 5, b_ = i & 31;
                hs[(j << 5) + (b_ ^ (j & 31))] = __ldcg(hsrc + i);
            }
            __syncthreads();
#pragma unroll 8
            for (int k = 0; k < 256; k++) {
                float4 w = wv[k];
                float hv = hs[(k << 5) + (b ^ (k & 31))];
                ai += w.x * hv;
                af += w.y * hv;
                ag += w.z * hv;
                ao += w.w * hv;
            }
        }
        const float* xrow = xp + (size_t)(b * TT + t) * GW;
        float gi = ai + xrow[jh];
        float gf = af + xrow[HW + jh];
        float gg = ag + xrow[2 * HW + jh];
        float go = ao + xrow[3 * HW + jh];
        c = sigf(gf) * c + sigf(gi) * tanhf(gg);
        float h = sigf(go) * tanhf(c);

        __stcg(g_h + (((((s + 1) & 1) * 2 + dir) << 13) + (jh << 5) + b), h);
        g_wh[((size_t)dir * BT + b * TT + t) * HW + jh] = h;

        if (s + 1 < TT) {
            // software grid barrier, absolute target (g_gen reset to 0 each launch)
            __threadfence();
            __syncthreads();
            if (tid == 0) {
                unsigned old = atomicAdd(&g_cnt, 1);
                if (old == NBW - 1) {
                    g_cnt = 0;
                    __threadfence();
                    g_gen = (unsigned)(s + 1);
                } else {
                    while (g_gen < (unsigned)(s + 1)) { __nanosleep(32); }
                }
            }
            __syncthreads();
            __threadfence();
        }
    }
}

// ---------------- feats = h @ W2t^T + b2t ----------------
__global__ void feats_kernel(const float* __restrict__ W2t, const float* __restrict__ b2t)
{
    int idx = blockIdx.x * blockDim.x + threadIdx.x;
    if (idx >= BT * KK) return;
    int bt = idx / KK, k = idx % KK;
    const float* hf = g_wh + (size_t)bt * HW;
    const float* hb = g_wh + ((size_t)BT + bt) * HW;
    const float* w = W2t + (size_t)k * HH;
    float acc = b2t[k];
#pragma unroll 4
    for (int j = 0; j < HW; j++) acc += hf[j] * w[j];
#pragma unroll 4
    for (int j = 0; j < HW; j++) acc += hb[j] * w[HW + j];
    g_feats[idx] = acc;
}

// ---------------- CRF forward + gold + final reduction ----------------
__global__ void crf_kernel(const int* __restrict__ tags, const float* __restrict__ trans,
                           float* __restrict__ out)
{
    __shared__ float res[BB];
    const int lane = threadIdx.x & 31;
    const int b = threadIdx.x >> 5;
    const unsigned full = 0xffffffffu;

    int kr = (lane < KK) ? lane : 0;
    float trow[KK];
#pragma unroll
    for (int j = 0; j < KK; j++) trow[j] = trans[kr * KK + j];

    float alpha = (lane == START_T) ? 0.0f : NEGV;

    for (int t = 0; t < TT; t++) {
        float vals[KK];
        float m = -INFINITY;
#pragma unroll
        for (int j = 0; j < KK; j++) {
            float aj = __shfl_sync(full, alpha, j);
            float v = aj + trow[j];
            vals[j] = v;
            m = fmaxf(m, v);
        }
        float s = 0.0f;
#pragma unroll
        for (int j = 0; j < KK; j++) s += expf(vals[j] - m);
        alpha = m + logf(s) + g_feats[(size_t)(b * TT + t) * KK + kr];
    }

    // fwd score = logsumexp(alpha + trans[STOP][:])
    float v = (lane < KK) ? (alpha + trans[STOP_T * KK + lane]) : -INFINITY;
    float m = v;
#pragma unroll
    for (int off = 16; off > 0; off >>= 1) m = fmaxf(m, __shfl_xor_sync(full, m, off));
    float e = (lane < KK) ? expf(v - m) : 0.0f;
#pragma unroll
    for (int off = 16; off > 0; off >>= 1) e += __shfl_xor_sync(full, e, off);
    float fwd = m + logf(e);

    // gold score
    float gold = 0.0f;
    for (int t = lane; t < TT; t += 32) {
        int tg = tags[b * TT + t];
        gold += g_feats[(size_t)(b * TT + t) * KK + tg];
        int prev = (t == 0) ? START_T : tags[b * TT + t - 1];
        gold += trans[tg * KK + prev];
    }
#pragma unroll
    for (int off = 16; off > 0; off >>= 1) gold += __shfl_xor_sync(full, gold, off);

    if (lane == 0) {
        gold += trans[STOP_T * KK + tags[b * TT + TT - 1]];
        res[b] = fwd - gold;
    }
    __syncthreads();
    if (threadIdx.x == 0) {
        float s = 0.0f;
        for (int i = 0; i < BB; i++) s += res[i];
        out[0] = s / (float)BB;
    }
}

// ---------------- launch ----------------
extern "C" void kernel_launch(void* const* d_in, const int* in_sizes, int n_in,
                              void* d_out, int out_size)
{
    const int*   sentence = (const int*)d_in[0];
    const int*   chars    = (const int*)d_in[1];
    const int*   tags     = (const int*)d_in[2];
    const float* word_emb = (const float*)d_in[3];
    const float* char_emb = (const float*)d_in[4];
    const float* c_Wih_f  = (const float*)d_in[5];
    const float* c_Whh_f  = (const float*)d_in[6];
    const float* c_b_f    = (const float*)d_in[7];
    const float* c_Wih_b  = (const float*)d_in[8];
    const float* c_Whh_b  = (const float*)d_in[9];   (void)c_Whh_b;
    const float* c_b_b    = (const float*)d_in[10];
    const float* w_Wih_f  = (const float*)d_in[11];
    const float* w_Whh_f  = (const float*)d_in[12];
    const float* w_b_f    = (const float*)d_in[13];
    const float* w_Wih_b  = (const float*)d_in[14];
    const float* w_Whh_b  = (const float*)d_in[15];
    const float* w_b_b    = (const float*)d_in[16];
    const float* W2t      = (const float*)d_in[17];
    const float* b2t      = (const float*)d_in[18];
    const float* trans    = (const float*)d_in[19];
    float* out = (float*)d_out;

    float* xprojc; cudaGetSymbolAddress((void**)&xprojc, g_xprojc);
    float* bg;     cudaGetSymbolAddress((void**)&bg, g_bg);
    float* chout;  cudaGetSymbolAddress((void**)&chout, g_chout);
    float* wx;     cudaGetSymbolAddress((void**)&wx, g_wx);
    float* wpf;    cudaGetSymbolAddress((void**)&wpf, g_wpf);
    float* wpb;    cudaGetSymbolAddress((void**)&wpb, g_wpb);

    // 1) char fwd input proj for all 16 char positions (gathered GEMM)
    gemm_tn<true><<<dim3(GC / 64, MCH / 64), 256>>>(char_emb, chars, 1, 0,
                                                    c_Wih_f, c_b_f, xprojc, MCH, GC, ECC);
    // 2) char bwd: gates for last char only
    gemm_tn<true><<<dim3(GC / 64, BT / 64), 256>>>(char_emb, chars, LCC, LCC - 1,
                                                   c_Wih_b, c_b_b, bg, BT, GC, ECC);
    // 3) char fwd recurrence
    char_fwd_kernel<<<BT, 256>>>(c_Whh_f, chout);
    // 4) char bwd single step
    char_bwd_kernel<<<(BT * HCD + 255) / 256, 256>>>(chout);
    // 5) build word input
    build_wx_kernel<<<(BT * INW + 255) / 256, 256>>>(sentence, word_emb);
    // 6-7) word input projections
    gemm_tn<false><<<dim3(GW / 64, BT / 64), 256>>>(wx, nullptr, 0, 0,
                                                    w_Wih_f, w_b_f, wpf, BT, GW, INW);
    gemm_tn<false><<<dim3(GW / 64, BT / 64), 256>>>(wx, nullptr, 0, 0,
                                                    w_Wih_b, w_b_b, wpb, BT, GW, INW);
    // 8) reset barrier state (determinism), then persistent word BiLSTM
    reset_bar<<<1, 1>>>();
    word_lstm_kernel<<<NBW, 128, 48 * 1024>>>(w_Whh_f, w_Whh_b);
    // 9) feats
    feats_kernel<<<(BT * KK + 255) / 256, 256>>>(W2t, b2t);
    // 10) CRF + output
    crf_kernel<<<1, BB * 32>>>(tags, trans, out);

    (void)in_sizes; (void)n_in; (void)out_size;
}

// round 4
// speedup vs baseline: 1.5322x; 1.5322x over previous
#include <cuda_runtime.h>
#include <cuda_bf16.h>
#include <cstdint>

// ---------------- problem constants ----------------
#define BB   32
#define TT   128
#define LCC  16
#define EE   256
#define ECC  64
#define VCC  128   // char vocab
#define HCC  128   // char bilstm out (64 per dir)
#define HH   512   // word bilstm out
#define KK   12
#define START_T 10
#define STOP_T  11
#define NEGV -10000.0f

#define BT   (BB*TT)            // 4096
#define INW  (EE + HCC)         // 384
#define HW   256                // word hidden per dir
#define GW   1024               // 4*HW
#define HCD  64                 // char hidden per dir
#define GC   256                // 4*HCD
#define NBW  128                // persistent blocks (grid barrier)

// ---------------- scratch ----------------
__device__ float g_ctab_f[VCC * GC];             // per-char fwd gate table
__device__ float g_ctab_b[VCC * GC];             // per-char bwd gate table
__device__ float g_chout[(size_t)BT * HCC];
__device__ float g_wx[(size_t)BT * INW];
__device__ float g_wpf[(size_t)BT * GW];         // layout [t][b][n]
__device__ float g_wpb[(size_t)BT * GW];         // layout [t][b][n]
__device__ float g_h[2 * 2 * HW * BB];           // [parity][dir][j][b]
__device__ float g_wh[(size_t)2 * BT * HW];      // [dir][b*T+t][j]
__device__ float g_feats[(size_t)BT * KK];

// barrier state (reset every launch -> deterministic across graph replays)
__device__ volatile unsigned g_gen = 0;
__device__ unsigned g_cnt = 0;

__device__ __forceinline__ float sigf(float x) { return 1.0f / (1.0f + expf(-x)); }

// ---------------- packed f32x2 helpers (sm_100+) ----------------
__device__ __forceinline__ unsigned long long fma2(unsigned long long a,
                                                   unsigned long long b,
                                                   unsigned long long c)
{
    unsigned long long d;
    asm("fma.rn.f32x2 %0, %1, %2, %3;" : "=l"(d) : "l"(a), "l"(b), "l"(c));
    return d;
}
__device__ __forceinline__ unsigned long long pack2(float x, float y)
{
    unsigned long long d;
    asm("mov.b64 %0, {%1, %2};" : "=l"(d) : "f"(x), "f"(y));
    return d;
}
__device__ __forceinline__ void unpack2(unsigned long long v, float& x, float& y)
{
    asm("mov.b64 {%0, %1}, %2;" : "=f"(x), "=f"(y) : "l"(v));
}

// ---------------- char projection tables: tab[cid][g] = emb[cid] @ Wih^T + b ----------------
__global__ void char_table_kernel(const float* __restrict__ char_emb,
                                  const float* __restrict__ Wih_f, const float* __restrict__ b_f,
                                  const float* __restrict__ Wih_b, const float* __restrict__ b_b)
{
    const int cid = blockIdx.x;
    const int dir = blockIdx.y;
    const int j = threadIdx.x;           // 0..255 gate index
    __shared__ float e[ECC];
    if (j < ECC) e[j] = char_emb[cid * ECC + j];
    __syncthreads();
    const float* Wih = dir ? Wih_b : Wih_f;
    const float* bias = dir ? b_b : b_f;
    const float* row = Wih + (size_t)j * ECC;
    float acc = bias[j];
#pragma unroll 8
    for (int k = 0; k < ECC; k++) acc += row[k] * e[k];
    (dir ? g_ctab_b : g_ctab_f)[cid * GC + j] = acc;
}

// ---------------- char BiLSTM (fwd recurrence + bwd single step), one block per word ----------------
__global__ void char_fwd_kernel(const int* __restrict__ chars,
                                const float* __restrict__ Whh, float* __restrict__ chout)
{
    const int bt = blockIdx.x;
    const int j = threadIdx.x;   // 256 threads = gate index
    __shared__ __align__(16) float hs[HCD];
    __shared__ float gs[GC];
    __shared__ int cid[LCC];

    if (j < LCC) cid[j] = chars[bt * LCC + j];

    float4 w4[16];
    const float4* wr = (const float4*)(Whh + (size_t)j * HCD);
#pragma unroll
    for (int i = 0; i < 16; i++) w4[i] = wr[i];

    float c = 0.0f;
    if (j < HCD) hs[j] = 0.0f;
    __syncthreads();

    for (int t = 0; t < LCC; t++) {
        float acc = g_ctab_f[cid[t] * GC + j];
#pragma unroll
        for (int kk = 0; kk < 16; kk++) {
            float4 h4 = *(const float4*)&hs[kk << 2];
            acc += w4[kk].x * h4.x + w4[kk].y * h4.y + w4[kk].z * h4.z + w4[kk].w * h4.w;
        }
        gs[j] = acc;
        __syncthreads();
        if (j < HCD) {
            float gi = gs[j], gf = gs[HCD + j], gg = gs[2 * HCD + j], go = gs[3 * HCD + j];
            c = sigf(gf) * c + sigf(gi) * tanhf(gg);
            hs[j] = sigf(go) * tanhf(c);
        }
        __syncthreads();
    }
    if (j < HCD) {
        chout[(size_t)bt * HCC + j] = hs[j];
        // backward dir: take-last == one step on last char from zero state
        const float* row = g_ctab_b + cid[LCC - 1] * GC;
        float gi = row[j], gg = row[2 * HCD + j], go = row[3 * HCD + j];
        float cb = sigf(gi) * tanhf(gg);
        chout[(size_t)bt * HCC + HCD + j] = sigf(go) * tanhf(cb);
    }
}

// ---------------- build word-lstm input x = [ch, we] ----------------
__global__ void build_wx_kernel(const int* __restrict__ sentence,
                                const float* __restrict__ word_emb)
{
    int idx = blockIdx.x * blockDim.x + threadIdx.x;
    if (idx >= BT * INW) return;
    int bt = idx / INW, cpos = idx % INW;
    float v;
    if (cpos < HCC) v = g_chout[(size_t)bt * HCC + cpos];
    else            v = word_emb[(size_t)sentence[bt] * EE + (cpos - HCC)];
    g_wx[idx] = v;
}

// ---------------- word projection GEMM: C = wx @ W^T + b, output layout [t][b][n] ----------------
// 128x128 tile, 256 threads, 8x8 microtile, packed f32x2 accumulators.
__global__ void wproj_gemm(const float* __restrict__ Wf, const float* __restrict__ bf_,
                           const float* __restrict__ Wb, const float* __restrict__ bb_)
{
    const float* W    = blockIdx.z ? Wb : Wf;
    const float* bias = blockIdx.z ? bb_ : bf_;
    float* C          = blockIdx.z ? g_wpb : g_wpf;

    __shared__ __align__(16) float As[16][128];
    __shared__ __align__(16) float Bs[16][128];

    const int m0 = blockIdx.y * 128;      // m = b*T + t; 128-aligned -> b fixed per block
    const int n0 = blockIdx.x * 128;
    const int bglob = blockIdx.y;         // batch index for this block
    const int tid = threadIdx.x;
    const int tx = tid & 15, ty = tid >> 4;

    unsigned long long acc2[8][4];
#pragma unroll
    for (int i = 0; i < 8; i++)
#pragma unroll
        for (int jp = 0; jp < 4; jp++) acc2[i][jp] = 0ull;

    for (int k0 = 0; k0 < INW; k0 += 16) {
#pragma unroll
        for (int u = 0; u < 2; u++) {
            int id = tid + u * 256;       // 0..511
            int row = id >> 2;            // 0..127
            int q = id & 3;               // float4 within row
            float4 a = *(const float4*)&g_wx[(size_t)(m0 + row) * INW + k0 + q * 4];
            As[q * 4 + 0][row] = a.x; As[q * 4 + 1][row] = a.y;
            As[q * 4 + 2][row] = a.z; As[q * 4 + 3][row] = a.w;
            float4 w = *(const float4*)&W[(size_t)(n0 + row) * INW + k0 + q * 4];
            Bs[q * 4 + 0][row] = w.x; Bs[q * 4 + 1][row] = w.y;
            Bs[q * 4 + 2][row] = w.z; Bs[q * 4 + 3][row] = w.w;
        }
        __syncthreads();
#pragma unroll
        for (int k = 0; k < 16; k++) {
            float4 a0 = *(const float4*)&As[k][ty * 8];
            float4 a1 = *(const float4*)&As[k][ty * 8 + 4];
            ulonglong2 b0 = *(const ulonglong2*)&Bs[k][tx * 8];
            ulonglong2 b1 = *(const ulonglong2*)&Bs[k][tx * 8 + 4];
            float aarr[8] = {a0.x, a0.y, a0.z, a0.w, a1.x, a1.y, a1.z, a1.w};
#pragma unroll
            for (int i = 0; i < 8; i++) {
                unsigned long long ad = pack2(aarr[i], aarr[i]);
                acc2[i][0] = fma2(ad, b0.x, acc2[i][0]);
                acc2[i][1] = fma2(ad, b0.y, acc2[i][1]);
                acc2[i][2] = fma2(ad, b1.x, acc2[i][2]);
                acc2[i][3] = fma2(ad, b1.y, acc2[i][3]);
            }
        }
        __syncthreads();
    }

#pragma unroll
    for (int i = 0; i < 8; i++) {
        int t = ty * 8 + i;               // local m == t (b fixed)
        size_t base = ((size_t)t * BB + bglob) * GW;
#pragma unroll
        for (int jp = 0; jp < 4; jp++) {
            int n = n0 + tx * 8 + jp * 2;
            float c0, c1;
            unpack2(acc2[i][jp], c0, c1);
            float2 v = make_float2(c0 + __ldg(&bias[n]), c1 + __ldg(&bias[n + 1]));
            *(float2*)&C[base + n] = v;
        }
    }
}

// ---------------- barrier reset (determinism across graph replays) ----------------
__global__ void reset_bar()
{
    g_cnt = 0;
    g_gen = 0;
}

// ---------------- persistent word BiLSTM with proven atomic grid barrier ----------------
__global__ void word_lstm_kernel(const float* __restrict__ Whhf,
                                 const float* __restrict__ Whhb)
{
    extern __shared__ float sm[];
    float* ws = sm;                 // 4096 floats: [jh_l][k][gate(4)]
    float* hs = sm + 4096;          // 8192 floats: [k][b]

    const int tid = threadIdx.x;          // 0..127
    const int dir = blockIdx.x >> 6;
    const int chunk = blockIdx.x & 63;
    const int jh0 = chunk * 4;
    const int jh_l = tid >> 5;            // 0..3
    const int b = tid & 31;
    const int jh = jh0 + jh_l;

    const float* Whh = dir ? Whhb : Whhf;
    const float* xp  = dir ? g_wpb : g_wpf;

    // stage weight slice once: ws[jl*1024 + k*4 + gate]
    for (int i = tid; i < 4096; i += 128) {
        int gate = i & 3;
        int k = (i >> 2) & 255;
        int jl = i >> 10;
        ws[i] = Whh[(size_t)((gate << 8) + jh0 + jl) * HW + k];
    }
    __syncthreads();

    const ulonglong2* wv = (const ulonglong2*)ws + (jh_l << 8);

    float xi, xf2, xg, xo;
    {
        int t0 = dir ? (TT - 1) : 0;
        const float* base = xp + ((size_t)t0 * BB + b) * GW;
        xi = base[jh]; xf2 = base[HW + jh]; xg = base[2 * HW + jh]; xo = base[3 * HW + jh];
    }

    float c = 0.0f;
    for (int s = 0; s < TT; s++) {
        const int t = dir ? (TT - 1 - s) : s;
        unsigned long long acc_if = pack2(xi, xf2);
        unsigned long long acc_go = pack2(xg, xo);
        if (s > 0) {
            const float4* hsrc = (const float4*)(g_h + (((s & 1) * 2 + dir) << 13));
            float4* hd4 = (float4*)hs;
#pragma unroll
            for (int i = tid; i < 2048; i += 128) hd4[i] = __ldcg(hsrc + i);
            __syncthreads();
#pragma unroll 8
            for (int k = 0; k < 256; k++) {
                ulonglong2 w = wv[k];
                float hv = hs[(k << 5) + b];
                unsigned long long hd = pack2(hv, hv);
                acc_if = fma2(hd, w.x, acc_if);
                acc_go = fma2(hd, w.y, acc_go);
            }
        }
        float gi, gf, gg, go;
        unpack2(acc_if, gi, gf);
        unpack2(acc_go, gg, go);
        c = sigf(gf) * c + sigf(gi) * tanhf(gg);
        float h = sigf(go) * tanhf(c);

        __stcg(g_h + (((((s + 1) & 1) * 2 + dir) << 13) + (jh << 5) + b), h);
        g_wh[((size_t)dir * BT + b * TT + t) * HW + jh] = h;

        if (s + 1 < TT) {
            // prefetch next x while we wait at the barrier
            int tn = dir ? (TT - 2 - s) : (s + 1);
            const float* base = xp + ((size_t)tn * BB + b) * GW;
            xi = base[jh]; xf2 = base[HW + jh]; xg = base[2 * HW + jh]; xo = base[3 * HW + jh];

            // proven atomic grid barrier, absolute target
            __threadfence();
            __syncthreads();
            if (tid == 0) {
                unsigned old = atomicAdd(&g_cnt, 1);
                if (old == NBW - 1) {
                    g_cnt = 0;
                    __threadfence();
                    g_gen = (unsigned)(s + 1);
                } else {
                    while (g_gen < (unsigned)(s + 1)) { __nanosleep(32); }
                }
            }
            __syncthreads();
            __threadfence();
        }
    }
}

// ---------------- feats: warp per (bt,k) dot over 512 ----------------
__global__ void feats_kernel(const float* __restrict__ W2t, const float* __restrict__ b2t)
{
    const unsigned full = 0xffffffffu;
    int gwarp = (blockIdx.x * blockDim.x + threadIdx.x) >> 5;
    if (gwarp >= BT * KK) return;
    int lane = threadIdx.x & 31;
    int bt = gwarp / KK, k = gwarp % KK;

    const float4* hf = (const float4*)(g_wh + (size_t)bt * HW);
    const float4* hb = (const float4*)(g_wh + ((size_t)BT + bt) * HW);
    const float4* w  = (const float4*)(W2t + (size_t)k * HH);

    float acc = 0.0f;
#pragma unroll
    for (int u = 0; u < 2; u++) {
        float4 h4 = hf[lane * 2 + u];
        float4 w4 = w[lane * 2 + u];
        acc += h4.x * w4.x + h4.y * w4.y + h4.z * w4.z + h4.w * w4.w;
    }
#pragma unroll
    for (int u = 0; u < 2; u++) {
        float4 h4 = hb[lane * 2 + u];
        float4 w4 = w[64 + lane * 2 + u];
        acc += h4.x * w4.x + h4.y * w4.y + h4.z * w4.z + h4.w * w4.w;
    }
#pragma unroll
    for (int off = 16; off > 0; off >>= 1) acc += __shfl_xor_sync(full, acc, off);
    if (lane == 0) g_feats[bt * KK + k] = acc + b2t[k];
}

// ---------------- CRF forward + gold + final reduction ----------------
__global__ void crf_kernel(const int* __restrict__ tags, const float* __restrict__ trans,
                           float* __restrict__ out)
{
    __shared__ float res[BB];
    const int lane = threadIdx.x & 31;
    const int b = threadIdx.x >> 5;
    const unsigned full = 0xffffffffu;

    int kr = (lane < KK) ? lane : 0;
    float trow[KK];
#pragma unroll
    for (int j = 0; j < KK; j++) trow[j] = trans[kr * KK + j];

    float alpha = (lane == START_T) ? 0.0f : NEGV;

    for (int t = 0; t < TT; t++) {
        float vals[KK];
        float m = -INFINITY;
#pragma unroll
        for (int j = 0; j < KK; j++) {
            float aj = __shfl_sync(full, alpha, j);
            float v = aj + trow[j];
            vals[j] = v;
            m = fmaxf(m, v);
        }
        float s = 0.0f;
#pragma unroll
        for (int j = 0; j < KK; j++) s += expf(vals[j] - m);
        alpha = m + logf(s) + g_feats[(size_t)(b * TT + t) * KK + kr];
    }

    float v = (lane < KK) ? (alpha + trans[STOP_T * KK + lane]) : -INFINITY;
    float m = v;
#pragma unroll
    for (int off = 16; off > 0; off >>= 1) m = fmaxf(m, __shfl_xor_sync(full, m, off));
    float e = (lane < KK) ? expf(v - m) : 0.0f;
#pragma unroll
    for (int off = 16; off > 0; off >>= 1) e += __shfl_xor_sync(full, e, off);
    float fwd = m + logf(e);

    float gold = 0.0f;
    for (int t = lane; t < TT; t += 32) {
        int tg = tags[b * TT + t];
        gold += g_feats[(size_t)(b * TT + t) * KK + tg];
        int prev = (t == 0) ? START_T : tags[b * TT + t - 1];
        gold += trans[tg * KK + prev];
    }
#pragma unroll
    for (int off = 16; off > 0; off >>= 1) gold += __shfl_xor_sync(full, gold, off);

    if (lane == 0) {
        gold += trans[STOP_T * KK + tags[b * TT + TT - 1]];
        res[b] = fwd - gold;
    }
    __syncthreads();
    if (threadIdx.x == 0) {
        float s = 0.0f;
        for (int i = 0; i < BB; i++) s += res[i];
        out[0] = s / (float)BB;
    }
}

// ---------------- launch ----------------
extern "C" void kernel_launch(void* const* d_in, const int* in_sizes, int n_in,
                              void* d_out, int out_size)
{
    const int*   sentence = (const int*)d_in[0];
    const int*   chars    = (const int*)d_in[1];
    const int*   tags     = (const int*)d_in[2];
    const float* word_emb = (const float*)d_in[3];
    const float* char_emb = (const float*)d_in[4];
    const float* c_Wih_f  = (const float*)d_in[5];
    const float* c_Whh_f  = (const float*)d_in[6];
    const float* c_b_f    = (const float*)d_in[7];
    const float* c_Wih_b  = (const float*)d_in[8];
    const float* c_Whh_b  = (const float*)d_in[9];   (void)c_Whh_b;
    const float* c_b_b    = (const float*)d_in[10];
    const float* w_Wih_f  = (const float*)d_in[11];
    const float* w_Whh_f  = (const float*)d_in[12];
    const float* w_b_f    = (const float*)d_in[13];
    const float* w_Wih_b  = (const float*)d_in[14];
    const float* w_Whh_b  = (const float*)d_in[15];
    const float* w_b_b    = (const float*)d_in[16];
    const float* W2t      = (const float*)d_in[17];
    const float* b2t      = (const float*)d_in[18];
    const float* trans    = (const float*)d_in[19];
    float* out = (float*)d_out;

    float* chout; cudaGetSymbolAddress((void**)&chout, g_chout);

    // 1) char gate tables (both dirs)
    char_table_kernel<<<dim3(VCC, 2), GC>>>(char_emb, c_Wih_f, c_b_f, c_Wih_b, c_b_b);
    // 2) char BiLSTM (fwd recurrence + bwd single step), table-driven
    char_fwd_kernel<<<BT, GC>>>(chars, c_Whh_f, chout);
    // 3) build word input
    build_wx_kernel<<<(BT * INW + 255) / 256, 256>>>(sentence, word_emb);
    // 4) word input projections (both dirs in one launch)
    wproj_gemm<<<dim3(GW / 128, BT / 128, 2), 256>>>(w_Wih_f, w_b_f, w_Wih_b, w_b_b);
    // 5) barrier reset + persistent word BiLSTM
    reset_bar<<<1, 1>>>();
    word_lstm_kernel<<<NBW, 128, 48 * 1024>>>(w_Whh_f, w_Whh_b);
    // 6) feats
    feats_kernel<<<(BT * KK * 32 + 255) / 256, 256>>>(W2t, b2t);
    // 7) CRF + output
    crf_kernel<<<1, BB * 32>>>(tags, trans, out);

    (void)in_sizes; (void)n_in; (void)out_size;
}